// round 13
// baseline (speedup 1.0000x reference)
#include <cuda_runtime.h>
#include <math.h>

#define FDIM 256
#define BMAX 1024
#define NMAX 1048576
#define WST 260           // sW stride (256 data + 4 pad): 16B-aligned rows, conflict-free LDS.128
#define RT 32             // rows per CTA tile

typedef unsigned long long ull;

// ---------------- scratch (static device globals; no allocation) ----------------
__device__ __align__(128) float g_t1k[BMAX * FDIM];
__device__ __align__(128) float g_t1v[BMAX * FDIM];
__device__ __align__(128) float g_rk [BMAX * FDIM];
__device__ __align__(128) float g_rv [BMAX * FDIM];
__device__ __align__(128) float g_km [BMAX * FDIM];
__device__ __align__(128) float g_vm [BMAX * FDIM];
__device__ __align__(128) float g_kq [BMAX * FDIM];
__device__ __align__(128) float g_dot[NMAX];

__device__ __forceinline__ float actf(float x) {
    return x / (1.0f + expf(-1.702f * x));
}
__device__ __forceinline__ ull ffma2(ull a, ull b, ull c) {
    ull d;
    asm("fma.rn.f32x2 %0, %1, %2, %3;" : "=l"(d) : "l"(a), "l"(b), "l"(c));
    return d;
}
__device__ __forceinline__ float pairsum(ull v) {
    float2 f = *(float2*)&v;
    return f.x + f.y;
}
__device__ __forceinline__ float dot4(float4 a, float4 b) {
    return a.x * b.x + a.y * b.y + a.z * b.z + a.w * b.w;
}

// ================= col-tiled layer GEMM (register double-buffered) =================
// C[row0+r][f0+c] = post( A[row0+r,:] . Wrow(f0+c, :) + bias[f0+c] )
// grid: (8 colTiles, rowTiles(RT), nbranch). block 256: warp = 4 rows, lane = col.
// mode bits: 1 = A is entry rank1 act(E*ewf+ebf); 2 = add rank1 residual in epilogue;
//            4 = apply act; 8 = W is k-major (Wrow(c,k) = W[k][c]) else row-major W[c][k].
__global__ __launch_bounds__(256, 2)
void layer_kernel(const float* __restrict__ A0, const float* __restrict__ A1,
                  const float* __restrict__ W0, const float* __restrict__ W1,
                  const float* __restrict__ b0, const float* __restrict__ b1,
                  const float* __restrict__ E,
                  const float* __restrict__ ef0, const float* __restrict__ eb0,
                  const float* __restrict__ ef1, const float* __restrict__ eb1,
                  float* __restrict__ C0, float* __restrict__ C1,
                  int B, int mode) {
    extern __shared__ __align__(16) float sm[];
    float* sW = sm;                 // 32 x WST
    float* sA = sm + 32 * WST;      // RT x 256

    int br = blockIdx.z;
    const float* A    = br ? A1 : A0;
    const float* W    = br ? W1 : W0;
    const float* bias = br ? b1 : b0;
    const float* ewf  = br ? ef1 : ef0;
    const float* ebf  = br ? eb1 : eb0;
    float*       C    = br ? C1 : C0;

    int t    = threadIdx.x;
    int f0   = blockIdx.x * 32;
    int row0 = blockIdx.y * RT;

    // ---- stage W tile ----
    if (mode & 8) {
        // k-major: sW[c][k] = W[k][f0+c]; warp reads 32 consecutive cols per k (coalesced)
        int lane = t & 31, w = t >> 5;
        #pragma unroll 8
        for (int i = 0; i < 32; i++) {
            int k = i * 8 + w;
            sW[lane * WST + k] = W[(size_t)k * FDIM + f0 + lane];
        }
    } else {
        const float4* W4 = (const float4*)W;
        #pragma unroll
        for (int i = 0; i < 8; i++) {
            int idx = i * 256 + t;      // 0..2047
            int row = idx >> 6;
            int k4  = idx & 63;
            float4 v = W4[(size_t)(f0 + row) * 64 + k4];
            *(float4*)(sW + row * WST + k4 * 4) = v;
        }
    }

    // ---- stage A tile: rows row0..row0+RT-1 ----
    if (mode & 1) {
        const float4* ew4 = (const float4*)ewf;
        const float4* eb4 = (const float4*)ebf;
        #pragma unroll
        for (int i = 0; i < RT * 64 / 256; i++) {
            int idx = i * 256 + t;
            int r   = idx >> 6;
            int k4  = idx & 63;
            float e = (row0 + r < B) ? __ldg(E + row0 + r) : 0.f;
            float4 w = __ldg(ew4 + k4);
            float4 bb = ebf ? __ldg(eb4 + k4) : make_float4(0.f, 0.f, 0.f, 0.f);
            float4 o;
            o.x = actf(e * w.x + bb.x);
            o.y = actf(e * w.y + bb.y);
            o.z = actf(e * w.z + bb.z);
            o.w = actf(e * w.w + bb.w);
            *(float4*)(sA + r * 256 + k4 * 4) = o;
        }
    } else {
        const float4* A4 = (const float4*)A;
        #pragma unroll
        for (int i = 0; i < RT * 64 / 256; i++) {
            int idx = i * 256 + t;
            int r   = idx >> 6;
            int k4  = idx & 63;
            float4 v;
            if (row0 + r < B) v = A4[(size_t)(row0 + r) * 64 + k4];
            else              v = make_float4(0.f, 0.f, 0.f, 0.f);
            *(float4*)(sA + r * 256 + k4 * 4) = v;
        }
    }
    __syncthreads();

    // ---- compute: warp rq -> rows rq*4..+3; lane c -> col f0+c ----
    int c  = t & 31;
    int rq = t >> 5;
    const float* wr = sW + c * WST;
    const float* ar = sA + (rq * 4) * 256;

    ull acc[4][2] = {{0,0},{0,0},{0,0},{0,0}};

    ulonglong2 w_cur = *(const ulonglong2*)(wr);
    ulonglong2 a_cur[4];
    #pragma unroll
    for (int r = 0; r < 4; r++)
        a_cur[r] = *(const ulonglong2*)(ar + r * 256);

    #pragma unroll
    for (int kk = 0; kk < 64; kk++) {        // 4 k per iter
        ulonglong2 w_nxt;
        ulonglong2 a_nxt[4];
        if (kk < 63) {
            w_nxt = *(const ulonglong2*)(wr + (kk + 1) * 4);
            #pragma unroll
            for (int r = 0; r < 4; r++)
                a_nxt[r] = *(const ulonglong2*)(ar + r * 256 + (kk + 1) * 4);
        }
        #pragma unroll
        for (int r = 0; r < 4; r++) {
            acc[r][0] = ffma2(a_cur[r].x, w_cur.x, acc[r][0]);
            acc[r][1] = ffma2(a_cur[r].y, w_cur.y, acc[r][1]);
        }
        if (kk < 63) {
            w_cur = w_nxt;
            #pragma unroll
            for (int r = 0; r < 4; r++) a_cur[r] = a_nxt[r];
        }
    }

    // ---- epilogue ----
    float o[4];
    #pragma unroll
    for (int r = 0; r < 4; r++)
        o[r] = pairsum(acc[r][0]) + pairsum(acc[r][1]);

    float bb = bias ? __ldg(bias + f0 + c) : 0.f;
    float rw = 0.f, rb = 0.f;
    if (mode & 2) {
        rw = __ldg(ewf + f0 + c);
        if (ebf) rb = __ldg(ebf + f0 + c);
    }
    #pragma unroll
    for (int i = 0; i < 4; i++) {
        int row = row0 + rq * 4 + i;
        if (row >= B) continue;
        float v = o[i] + bb;
        if (mode & 2) v += __ldg(E + row) * rw + rb;
        if (mode & 4) v = actf(v);
        C[(size_t)row * 256 + f0 + c] = v;
    }
}

// ---------------- seg helpers (int32 buffer that may really be int64) ----------------
__device__ __forceinline__ int seg_is64(const int* __restrict__ s, int N) {
    return s[N - 1] == 0;   // sorted, max=B-1>0; int64 LE high word at N-1 is 0
}

// ---------------- dot pass: 32 rows/warp, kq register-cached, streaming x ------------
__global__ void dot_kernel(const float4* __restrict__ x,
                           const int* __restrict__ seg32,
                           const float* __restrict__ kq,
                           float* __restrict__ dotv,
                           int N) {
    int gw   = (blockIdx.x * blockDim.x + threadIdx.x) >> 5;
    int lane = threadIdx.x & 31;
    int row0 = gw * 32;
    if (row0 >= N) return;
    int st = seg_is64(seg32, N) ? 2 : 1;

    int rlast = row0 + 31 < N ? row0 + 31 : N - 1;
    int b0    = seg32[(size_t)row0 * st];
    int blast = seg32[(size_t)rlast * st];

    if (b0 == blast && row0 + 32 <= N) {
        const float4* kr = (const float4*)kq + (size_t)b0 * 64;
        float4 k0 = kr[lane], k1 = kr[lane + 32];
        float myres = 0.f;
        #pragma unroll
        for (int batch = 0; batch < 4; batch++) {
            float4 xa[8], xb[8];
            #pragma unroll
            for (int r = 0; r < 8; r++) {
                const float4* xr = x + (size_t)(row0 + batch * 8 + r) * 64;
                xa[r] = __ldcs(xr + lane);
                xb[r] = __ldcs(xr + lane + 32);
            }
            float s[8];
            #pragma unroll
            for (int r = 0; r < 8; r++)
                s[r] = dot4(xa[r], k0) + dot4(xb[r], k1);
            #pragma unroll
            for (int o = 16; o; o >>= 1) {
                #pragma unroll
                for (int r = 0; r < 8; r++)
                    s[r] += __shfl_xor_sync(0xffffffffu, s[r], o);
            }
            #pragma unroll
            for (int r = 0; r < 8; r++)
                if (lane == batch * 8 + r) myres = s[r];
        }
        dotv[row0 + lane] = myres;
    } else {
        int nrows = N - row0; if (nrows > 32) nrows = 32;
        int myrow = row0 + lane;
        int rload = myrow < N ? myrow : N - 1;
        int bl = seg32[(size_t)rload * st];
        int bcur = -1;
        float4 k0, k1;
        float myres = 0.f;
        for (int r = 0; r < nrows; r++) {
            int b = __shfl_sync(0xffffffffu, bl, r);
            if (b != bcur) {
                const float4* kr = (const float4*)kq + (size_t)b * 64;
                k0 = kr[lane]; k1 = kr[lane + 32];
                bcur = b;
            }
            const float4* xr = x + (size_t)(row0 + r) * 64;
            float4 a0 = __ldcs(xr + lane), a1 = __ldcs(xr + lane + 32);
            float s = dot4(a0, k0) + dot4(a1, k1);
            #pragma unroll
            for (int o = 16; o; o >>= 1) s += __shfl_xor_sync(0xffffffffu, s, o);
            if (lane == r) myres = s;
        }
        if (myrow < N) dotv[myrow] = myres;
    }
}

// ---------------- fused segment reduce + output ----------------
// Block b owns segment b = contiguous range [lb(b), lb(b+1)).
// Pass 1: deterministic max; pass 2: deterministic expsum; pass 3: write output
// rows with vm row register-cached per warp and lane-parallel coef precompute.
__device__ __forceinline__ int lowerb(const int* __restrict__ s, int n, int v, int st) {
    int lo = 0, hi = n;
    while (lo < hi) {
        int mid = (lo + hi) >> 1;
        if (s[(size_t)mid * st] < v) lo = mid + 1; else hi = mid;
    }
    return lo;
}

__global__ __launch_bounds__(256)
void segout_kernel(const int* __restrict__ seg32,
                   const float* __restrict__ dotv,
                   const float* __restrict__ vm,
                   float4* __restrict__ out,
                   int N, float scale) {
    __shared__ float red[256];
    __shared__ int sse[2];
    __shared__ float sparm[2];     // mx, inv
    int b = blockIdx.x;
    int t = threadIdx.x;
    int lane = t & 31;
    int w    = t >> 5;

    if (t == 0) {
        int st = seg_is64(seg32, N) ? 2 : 1;
        sse[0] = lowerb(seg32, N, b, st);
        sse[1] = lowerb(seg32, N, b + 1, st);
    }
    __syncthreads();
    int start = sse[0], end = sse[1];

    // pass 1: max
    float m = -3.4e38f;
    for (int i = start + t; i < end; i += 256) m = fmaxf(m, dotv[i]);
    red[t] = m;
    __syncthreads();
    #pragma unroll
    for (int s = 128; s; s >>= 1) {
        if (t < s) red[t] = fmaxf(red[t], red[t + s]);
        __syncthreads();
    }
    float mx = red[0];
    __syncthreads();

    // pass 2: expsum
    float ss = 0.f;
    for (int i = start + t; i < end; i += 256) ss += expf((dotv[i] - mx) * scale);
    red[t] = ss;
    __syncthreads();
    #pragma unroll
    for (int s = 128; s; s >>= 1) {
        if (t < s) red[t] += red[t + s];
        __syncthreads();
    }
    if (t == 0) {
        sparm[0] = mx;
        sparm[1] = 1.f / (red[0] + 1e-8f);
    }
    __syncthreads();
    mx = sparm[0];
    float inv = sparm[1];

    // pass 3: output. vm row cached in registers; warps take 32-row chunks.
    const float4* vr = (const float4*)vm + (size_t)b * 64;
    float4 v0 = vr[lane], v1 = vr[lane + 32];

    for (int chunk = start + w * 32; chunk < end; chunk += 8 * 32) {
        int nrows = end - chunk; if (nrows > 32) nrows = 32;
        // lane-parallel coef precompute for this chunk
        float cl = 0.f;
        if (lane < nrows)
            cl = expf((dotv[chunk + lane] - mx) * scale) * inv;
        for (int r = 0; r < nrows; r++) {
            float cf = __shfl_sync(0xffffffffu, cl, r);
            float4 o0 = make_float4(v0.x * cf, v0.y * cf, v0.z * cf, v0.w * cf);
            float4 o1 = make_float4(v1.x * cf, v1.y * cf, v1.z * cf, v1.w * cf);
            float4* orow = out + (size_t)(chunk + r) * 64;
            __stcs(orow + lane, o0);
            __stcs(orow + lane + 32, o1);
        }
    }
}

// ---------------- launcher ----------------
extern "C" void kernel_launch(void* const* d_in, const int* in_sizes, int n_in,
                              void* d_out, int out_size) {
    int sh = (n_in >= 17) ? 0 : 1;
    const float* x    = (const float*)d_in[0];
    const float* E    = (const float*)d_in[1];
    const int*   seg  = (const int*)  d_in[3 - sh];
    const float* Wq   = (const float*)d_in[4 - sh];
    const float* Wkf  = (const float*)d_in[5 - sh];
    const float* bkf  = (const float*)d_in[6 - sh];
    const float* Wvf  = (const float*)d_in[7 - sh];
    const float* kW1  = (const float*)d_in[8 - sh];
    const float* kb1  = (const float*)d_in[9 - sh];
    const float* kW2  = (const float*)d_in[10 - sh];
    const float* kb2  = (const float*)d_in[11 - sh];
    const float* kWo  = (const float*)d_in[12 - sh];
    const float* kbo  = (const float*)d_in[13 - sh];
    const float* vW1  = (const float*)d_in[14 - sh];
    const float* vW2  = (const float*)d_in[15 - sh];
    const float* vWo  = (const float*)d_in[16 - sh];

    int B = in_sizes[1];
    int N = in_sizes[3 - sh];
    float scale = 1.f / 16.f;   // 1/sqrt(256)

    float *t1k, *t1v, *rk, *rv, *km, *vm, *kq, *dotv;
    cudaGetSymbolAddress((void**)&t1k, g_t1k);
    cudaGetSymbolAddress((void**)&t1v, g_t1v);
    cudaGetSymbolAddress((void**)&rk,  g_rk);
    cudaGetSymbolAddress((void**)&rv,  g_rv);
    cudaGetSymbolAddress((void**)&km,  g_km);
    cudaGetSymbolAddress((void**)&vm,  g_vm);
    cudaGetSymbolAddress((void**)&kq,  g_kq);
    cudaGetSymbolAddress((void**)&dotv, g_dot);

    const int LS = (32 * WST + RT * 256) * (int)sizeof(float);   // 66048 B
    cudaFuncSetAttribute(layer_kernel, cudaFuncAttributeMaxDynamicSharedMemorySize, LS);

    int rowTiles = (B + RT - 1) / RT;

    // 1) L1: t1 = act( entry(E) @ W1^T + b1 )
    dim3 lg(8, rowTiles, 2);
    layer_kernel<<<lg, 256, LS>>>(nullptr, nullptr, kW1, vW1, kb1, nullptr, E,
                                  Wkf, bkf, Wvf, nullptr, t1k, t1v, B, 1 | 4);
    // 2) L2: r = act( rank1(E) + t1 @ W2^T + b2 )
    layer_kernel<<<lg, 256, LS>>>(t1k, t1v, kW2, vW2, kb2, nullptr, E,
                                  Wkf, bkf, Wvf, nullptr, rk, rv, B, 2 | 4);
    // 3) L3: km = r @ Wo^T + bo ; vm = r @ vWo^T
    layer_kernel<<<lg, 256, LS>>>(rk, rv, kWo, vWo, kbo, nullptr, E,
                                  nullptr, nullptr, nullptr, nullptr, km, vm, B, 0);
    // 4) L4 (k only): kq = km @ Wq  (k-major W staging, no pre-transpose)
    dim3 lg4(8, rowTiles, 1);
    layer_kernel<<<lg4, 256, LS>>>(km, km, Wq, Wq, nullptr, nullptr, E,
                                   nullptr, nullptr, nullptr, nullptr, kq, kq, B, 8);

    // 5) dot pass
    {
        int warps = (N + 31) / 32;
        int blocks = (warps * 32 + 255) / 256;
        dot_kernel<<<blocks, 256>>>((const float4*)x, seg, kq, dotv, N);
    }
    // 6) fused segment reduce + output
    segout_kernel<<<B, 256>>>(seg, dotv, vm, (float4*)d_out, N, scale);
}

// round 14
// speedup vs baseline: 1.0318x; 1.0318x over previous
#include <cuda_runtime.h>
#include <math.h>

#define FDIM 256
#define BMAX 1024
#define NMAX 1048576
#define WST 260           // sW stride (256 data + 4 pad): 16B-aligned, conflict-free LDS.128
#define RT 32             // rows per CTA tile

typedef unsigned long long ull;

// ---------------- scratch (static device globals; no allocation) ----------------
__device__ __align__(128) float g_t1k[BMAX * FDIM];
__device__ __align__(128) float g_t1v[BMAX * FDIM];
__device__ __align__(128) float g_rk [BMAX * FDIM];
__device__ __align__(128) float g_rv [BMAX * FDIM];
__device__ __align__(128) float g_km [BMAX * FDIM];
__device__ __align__(128) float g_vm [BMAX * FDIM];
__device__ __align__(128) float g_kq [BMAX * FDIM];
__device__ __align__(128) float g_wqT[FDIM * FDIM];
__device__ __align__(128) float g_dot[NMAX];
__device__ __align__(128) float g_smax[BMAX];
__device__ __align__(128) float g_inv [BMAX];

__device__ __forceinline__ float actf(float x) {
    return x / (1.0f + expf(-1.702f * x));
}
__device__ __forceinline__ ull ffma2(ull a, ull b, ull c) {
    ull d;
    asm("fma.rn.f32x2 %0, %1, %2, %3;" : "=l"(d) : "l"(a), "l"(b), "l"(c));
    return d;
}
__device__ __forceinline__ float pairsum(ull v) {
    float2 f = *(float2*)&v;
    return f.x + f.y;
}
__device__ __forceinline__ float dot4(float4 a, float4 b) {
    return a.x * b.x + a.y * b.y + a.z * b.z + a.w * b.w;
}

// ---------------- transpose 256x256 (for Wq) ----------------
__global__ void transpose256_kernel(const float* __restrict__ in, float* __restrict__ out) {
    __shared__ float tile[32][33];
    int bx = (blockIdx.x & 7) * 32;
    int by = (blockIdx.x >> 3) * 32;
    int tx = threadIdx.x & 31, ty = threadIdx.x >> 5;
    #pragma unroll
    for (int i = 0; i < 32; i += 8)
        tile[ty + i][tx] = in[(size_t)(by + ty + i) * 256 + bx + tx];
    __syncthreads();
    #pragma unroll
    for (int i = 0; i < 32; i += 8)
        out[(size_t)(bx + ty + i) * 256 + by + tx] = tile[tx][ty + i];
}

// ================= col-tiled layer GEMM (register double-buffered) =================
// C[row0+r][f0+c] = post( A[row0+r,:] . W[f0+c,:] + bias[f0+c] )
// grid: (8 colTiles, rowTiles(RT), 1). block 256: warp = 4 rows, lane = col.
// mode bits: 1 = A is entry rank1 act(E*ewf+ebf); 2 = add rank1 residual in epilogue;
//            4 = apply act.
__global__ __launch_bounds__(256, 2)
void layer_kernel(const float* __restrict__ A,
                  const float* __restrict__ W,
                  const float* __restrict__ bias,
                  const float* __restrict__ E,
                  const float* __restrict__ ewf, const float* __restrict__ ebf,
                  float* __restrict__ C,
                  int B, int mode) {
    extern __shared__ __align__(16) float sm[];
    float* sW = sm;                 // 32 x WST
    float* sA = sm + 32 * WST;      // RT x 256

    int t    = threadIdx.x;
    int f0   = blockIdx.x * 32;
    int row0 = blockIdx.y * RT;

    // ---- stage W tile: rows f0..f0+31, all 256 k (coalesced LDG.128 -> STS.128) ----
    {
        const float4* W4 = (const float4*)W;
        #pragma unroll
        for (int i = 0; i < 8; i++) {
            int idx = i * 256 + t;      // 0..2047
            int row = idx >> 6;
            int k4  = idx & 63;
            float4 v = W4[(size_t)(f0 + row) * 64 + k4];
            *(float4*)(sW + row * WST + k4 * 4) = v;
        }
    }

    // ---- stage A tile: rows row0..row0+RT-1 ----
    if (mode & 1) {
        const float4* ew4 = (const float4*)ewf;
        const float4* eb4 = (const float4*)ebf;
        #pragma unroll
        for (int i = 0; i < RT * 64 / 256; i++) {
            int idx = i * 256 + t;
            int r   = idx >> 6;
            int k4  = idx & 63;
            float e = (row0 + r < B) ? __ldg(E + row0 + r) : 0.f;
            float4 w = __ldg(ew4 + k4);
            float4 bb = ebf ? __ldg(eb4 + k4) : make_float4(0.f, 0.f, 0.f, 0.f);
            float4 o;
            o.x = actf(e * w.x + bb.x);
            o.y = actf(e * w.y + bb.y);
            o.z = actf(e * w.z + bb.z);
            o.w = actf(e * w.w + bb.w);
            *(float4*)(sA + r * 256 + k4 * 4) = o;
        }
    } else {
        const float4* A4 = (const float4*)A;
        #pragma unroll
        for (int i = 0; i < RT * 64 / 256; i++) {
            int idx = i * 256 + t;
            int r   = idx >> 6;
            int k4  = idx & 63;
            float4 v;
            if (row0 + r < B) v = A4[(size_t)(row0 + r) * 64 + k4];
            else              v = make_float4(0.f, 0.f, 0.f, 0.f);
            *(float4*)(sA + r * 256 + k4 * 4) = v;
        }
    }
    __syncthreads();

    // ---- compute: warp rq -> rows rq*4..+3; lane c -> col f0+c ----
    int c  = t & 31;
    int rq = t >> 5;
    const float* wr = sW + c * WST;
    const float* ar = sA + (rq * 4) * 256;

    ull acc[4][2] = {{0,0},{0,0},{0,0},{0,0}};

    ulonglong2 w_cur = *(const ulonglong2*)(wr);
    ulonglong2 a_cur[4];
    #pragma unroll
    for (int r = 0; r < 4; r++)
        a_cur[r] = *(const ulonglong2*)(ar + r * 256);

    #pragma unroll
    for (int kk = 0; kk < 64; kk++) {        // 4 k per iter
        ulonglong2 w_nxt;
        ulonglong2 a_nxt[4];
        if (kk < 63) {
            w_nxt = *(const ulonglong2*)(wr + (kk + 1) * 4);
            #pragma unroll
            for (int r = 0; r < 4; r++)
                a_nxt[r] = *(const ulonglong2*)(ar + r * 256 + (kk + 1) * 4);
        }
        #pragma unroll
        for (int r = 0; r < 4; r++) {
            acc[r][0] = ffma2(a_cur[r].x, w_cur.x, acc[r][0]);
            acc[r][1] = ffma2(a_cur[r].y, w_cur.y, acc[r][1]);
        }
        if (kk < 63) {
            w_cur = w_nxt;
            #pragma unroll
            for (int r = 0; r < 4; r++) a_cur[r] = a_nxt[r];
        }
    }

    // ---- epilogue ----
    float o[4];
    #pragma unroll
    for (int r = 0; r < 4; r++)
        o[r] = pairsum(acc[r][0]) + pairsum(acc[r][1]);

    float bb = bias ? __ldg(bias + f0 + c) : 0.f;
    float rw = 0.f, rb = 0.f;
    if (mode & 2) {
        rw = __ldg(ewf + f0 + c);
        if (ebf) rb = __ldg(ebf + f0 + c);
    }
    #pragma unroll
    for (int i = 0; i < 4; i++) {
        int row = row0 + rq * 4 + i;
        if (row >= B) continue;
        float v = o[i] + bb;
        if (mode & 2) v += __ldg(E + row) * rw + rb;
        if (mode & 4) v = actf(v);
        C[(size_t)row * 256 + f0 + c] = v;
    }
}

// ---------------- seg helpers (int32 buffer that may really be int64) ----------------
__device__ __forceinline__ int seg_is64(const int* __restrict__ s, int N) {
    return s[N - 1] == 0;   // sorted, max=B-1>0; int64 LE high word at N-1 is 0
}

// ---------------- dot pass: 32 rows/warp, kq register-cached, streaming x ------------
__global__ void dot_kernel(const float4* __restrict__ x,
                           const int* __restrict__ seg32,
                           const float* __restrict__ kq,
                           float* __restrict__ dotv,
                           int N) {
    int gw   = (blockIdx.x * blockDim.x + threadIdx.x) >> 5;
    int lane = threadIdx.x & 31;
    int row0 = gw * 32;
    if (row0 >= N) return;
    int st = seg_is64(seg32, N) ? 2 : 1;

    int rlast = row0 + 31 < N ? row0 + 31 : N - 1;
    int b0    = seg32[(size_t)row0 * st];
    int blast = seg32[(size_t)rlast * st];

    if (b0 == blast && row0 + 32 <= N) {
        const float4* kr = (const float4*)kq + (size_t)b0 * 64;
        float4 k0 = kr[lane], k1 = kr[lane + 32];
        float myres = 0.f;
        #pragma unroll
        for (int batch = 0; batch < 4; batch++) {
            float4 xa[8], xb[8];
            #pragma unroll
            for (int r = 0; r < 8; r++) {
                const float4* xr = x + (size_t)(row0 + batch * 8 + r) * 64;
                xa[r] = __ldcs(xr + lane);
                xb[r] = __ldcs(xr + lane + 32);
            }
            float s[8];
            #pragma unroll
            for (int r = 0; r < 8; r++)
                s[r] = dot4(xa[r], k0) + dot4(xb[r], k1);
            #pragma unroll
            for (int o = 16; o; o >>= 1) {
                #pragma unroll
                for (int r = 0; r < 8; r++)
                    s[r] += __shfl_xor_sync(0xffffffffu, s[r], o);
            }
            #pragma unroll
            for (int r = 0; r < 8; r++)
                if (lane == batch * 8 + r) myres = s[r];
        }
        dotv[row0 + lane] = myres;
    } else {
        int nrows = N - row0; if (nrows > 32) nrows = 32;
        int myrow = row0 + lane;
        int rload = myrow < N ? myrow : N - 1;
        int bl = seg32[(size_t)rload * st];
        int bcur = -1;
        float4 k0, k1;
        float myres = 0.f;
        for (int r = 0; r < nrows; r++) {
            int b = __shfl_sync(0xffffffffu, bl, r);
            if (b != bcur) {
                const float4* kr = (const float4*)kq + (size_t)b * 64;
                k0 = kr[lane]; k1 = kr[lane + 32];
                bcur = b;
            }
            const float4* xr = x + (size_t)(row0 + r) * 64;
            float4 a0 = __ldcs(xr + lane), a1 = __ldcs(xr + lane + 32);
            float s = dot4(a0, k0) + dot4(a1, k1);
            #pragma unroll
            for (int o = 16; o; o >>= 1) s += __shfl_xor_sync(0xffffffffu, s, o);
            if (lane == r) myres = s;
        }
        if (myrow < N) dotv[myrow] = myres;
    }
}

// ---------------- segment reduce (deterministic, per-segment block) ----------------
__device__ __forceinline__ int lowerb(const int* __restrict__ s, int n, int v, int st) {
    int lo = 0, hi = n;
    while (lo < hi) {
        int mid = (lo + hi) >> 1;
        if (s[(size_t)mid * st] < v) lo = mid + 1; else hi = mid;
    }
    return lo;
}

__global__ void segreduce_kernel(const int* __restrict__ seg32,
                                 const float* __restrict__ dotv,
                                 float* __restrict__ smax,
                                 float* __restrict__ invnorm,
                                 int N, float scale) {
    __shared__ float red[256];
    __shared__ int sse[2];
    int b = blockIdx.x;
    int t = threadIdx.x;
    if (t == 0) {
        int st = seg_is64(seg32, N) ? 2 : 1;
        sse[0] = lowerb(seg32, N, b, st);
        sse[1] = lowerb(seg32, N, b + 1, st);
    }
    __syncthreads();
    int start = sse[0], end = sse[1];

    float m = -3.4e38f;
    for (int i = start + t; i < end; i += 256) m = fmaxf(m, dotv[i]);
    red[t] = m;
    __syncthreads();
    #pragma unroll
    for (int s = 128; s; s >>= 1) {
        if (t < s) red[t] = fmaxf(red[t], red[t + s]);
        __syncthreads();
    }
    float mx = red[0];
    __syncthreads();

    float ss = 0.f;
    for (int i = start + t; i < end; i += 256) ss += expf((dotv[i] - mx) * scale);
    red[t] = ss;
    __syncthreads();
    #pragma unroll
    for (int s = 128; s; s >>= 1) {
        if (t < s) red[t] += red[t + s];
        __syncthreads();
    }
    if (t == 0) {
        smax[b] = mx;
        invnorm[b] = 1.f / (red[0] + 1e-8f);
    }
}

// ---------------- output pass: 32 rows/warp, vm register-cached, streaming stores ----
__global__ void out_kernel(const float* __restrict__ dotv,
                           const int* __restrict__ seg32,
                           const float* __restrict__ vm,
                           const float* __restrict__ smax,
                           const float* __restrict__ invnorm,
                           float4* __restrict__ out,
                           int N, float scale) {
    int gw   = (blockIdx.x * blockDim.x + threadIdx.x) >> 5;
    int lane = threadIdx.x & 31;
    int row0 = gw * 32;
    if (row0 >= N) return;
    int st = seg_is64(seg32, N) ? 2 : 1;

    int myrow = row0 + lane;
    int bl = 0; float cl = 0.f;
    if (myrow < N) {
        bl = seg32[(size_t)myrow * st];
        cl = expf((dotv[myrow] - smax[bl]) * scale) * invnorm[bl];
    }

    int nrows = N - row0; if (nrows > 32) nrows = 32;
    int bcur = -1;
    float4 v0, v1;
    for (int r = 0; r < nrows; r++) {
        int b     = __shfl_sync(0xffffffffu, bl, r);
        float cf  = __shfl_sync(0xffffffffu, cl, r);
        if (b != bcur) {
            const float4* vr = (const float4*)vm + (size_t)b * 64;
            v0 = vr[lane];
            v1 = vr[lane + 32];
            bcur = b;
        }
        float4 o0 = make_float4(v0.x * cf, v0.y * cf, v0.z * cf, v0.w * cf);
        float4 o1 = make_float4(v1.x * cf, v1.y * cf, v1.z * cf, v1.w * cf);
        float4* orow = out + (size_t)(row0 + r) * 64;
        __stcs(orow + lane, o0);
        __stcs(orow + lane + 32, o1);
    }
}

// ---------------- launcher ----------------
extern "C" void kernel_launch(void* const* d_in, const int* in_sizes, int n_in,
                              void* d_out, int out_size) {
    int sh = (n_in >= 17) ? 0 : 1;
    const float* x    = (const float*)d_in[0];
    const float* E    = (const float*)d_in[1];
    const int*   seg  = (const int*)  d_in[3 - sh];
    const float* Wq   = (const float*)d_in[4 - sh];
    const float* Wkf  = (const float*)d_in[5 - sh];
    const float* bkf  = (const float*)d_in[6 - sh];
    const float* Wvf  = (const float*)d_in[7 - sh];
    const float* kW1  = (const float*)d_in[8 - sh];
    const float* kb1  = (const float*)d_in[9 - sh];
    const float* kW2  = (const float*)d_in[10 - sh];
    const float* kb2  = (const float*)d_in[11 - sh];
    const float* kWo  = (const float*)d_in[12 - sh];
    const float* kbo  = (const float*)d_in[13 - sh];
    const float* vW1  = (const float*)d_in[14 - sh];
    const float* vW2  = (const float*)d_in[15 - sh];
    const float* vWo  = (const float*)d_in[16 - sh];

    int B = in_sizes[1];
    int N = in_sizes[3 - sh];
    float scale = 1.f / 16.f;   // 1/sqrt(256)

    float *t1k, *t1v, *rk, *rv, *km, *vm, *kq, *wqT, *dotv, *smax, *inv;
    cudaGetSymbolAddress((void**)&t1k, g_t1k);
    cudaGetSymbolAddress((void**)&t1v, g_t1v);
    cudaGetSymbolAddress((void**)&rk,  g_rk);
    cudaGetSymbolAddress((void**)&rv,  g_rv);
    cudaGetSymbolAddress((void**)&km,  g_km);
    cudaGetSymbolAddress((void**)&vm,  g_vm);
    cudaGetSymbolAddress((void**)&kq,  g_kq);
    cudaGetSymbolAddress((void**)&wqT, g_wqT);
    cudaGetSymbolAddress((void**)&dotv, g_dot);
    cudaGetSymbolAddress((void**)&smax, g_smax);
    cudaGetSymbolAddress((void**)&inv,  g_inv);

    const int LS = (32 * WST + RT * 256) * (int)sizeof(float);   // 66048 B
    cudaFuncSetAttribute(layer_kernel, cudaFuncAttributeMaxDynamicSharedMemorySize, LS);

    // side stream + fork/join events (created once on the uncaptured
    // correctness call; capture sees only record/wait nodes — same work
    // every call)
    static cudaStream_t s_side = nullptr;
    static cudaEvent_t  s_fork = nullptr, s_join = nullptr;
    if (!s_side) {
        cudaStreamCreateWithFlags(&s_side, cudaStreamNonBlocking);
        cudaEventCreateWithFlags(&s_fork, cudaEventDisableTiming);
        cudaEventCreateWithFlags(&s_join, cudaEventDisableTiming);
    }

    int rowTiles = (B + RT - 1) / RT;
    dim3 lgrid(8, rowTiles, 1);

    // ---- fork: v-branch runs on the side stream ----
    cudaEventRecord(s_fork, 0);
    cudaStreamWaitEvent(s_side, s_fork, 0);

    layer_kernel<<<lgrid, 256, LS, s_side>>>(nullptr, vW1, nullptr, E,
                                             Wvf, nullptr, t1v, B, 1 | 4);
    layer_kernel<<<lgrid, 256, LS, s_side>>>(t1v, vW2, nullptr, E,
                                             Wvf, nullptr, rv, B, 2 | 4);
    layer_kernel<<<lgrid, 256, LS, s_side>>>(rv, vWo, nullptr, E,
                                             nullptr, nullptr, vm, B, 0);
    cudaEventRecord(s_join, s_side);

    // ---- main (legacy) stream: k-branch -> dot -> segreduce ----
    transpose256_kernel<<<64, 256>>>(Wq, wqT);
    layer_kernel<<<lgrid, 256, LS>>>(nullptr, kW1, kb1, E,
                                     Wkf, bkf, t1k, B, 1 | 4);
    layer_kernel<<<lgrid, 256, LS>>>(t1k, kW2, kb2, E,
                                     Wkf, bkf, rk, B, 2 | 4);
    layer_kernel<<<lgrid, 256, LS>>>(rk, kWo, kbo, E,
                                     nullptr, nullptr, km, B, 0);
    layer_kernel<<<lgrid, 256, LS>>>(km, wqT, nullptr, E,
                                     nullptr, nullptr, kq, B, 0);

    {
        int warps = (N + 31) / 32;
        int blocks = (warps * 32 + 255) / 256;
        dot_kernel<<<blocks, 256>>>((const float4*)x, seg, kq, dotv, N);
    }
    segreduce_kernel<<<B, 256>>>(seg, dotv, smax, inv, N, scale);

    // ---- join: out needs vm from the side stream ----
    cudaStreamWaitEvent(0, s_join, 0);
    {
        int warps = (N + 31) / 32;
        int blocks = (warps * 32 + 255) / 256;
        out_kernel<<<blocks, 256>>>(dotv, seg, vm, smax, inv, (float4*)d_out, N, scale);
    }
}

// round 15
// speedup vs baseline: 1.0499x; 1.0175x over previous
#include <cuda_runtime.h>
#include <math.h>

#define FDIM 256
#define BMAX 1024
#define NMAX 1048576
#define WST 260           // sW stride (256 data + 4 pad): 16B-aligned, conflict-free LDS.128
#define RT 32             // rows per CTA tile

typedef unsigned long long ull;

// ---------------- scratch (static device globals; no allocation) ----------------
__device__ __align__(128) float g_t1k[BMAX * FDIM];
__device__ __align__(128) float g_t1v[BMAX * FDIM];
__device__ __align__(128) float g_rk [BMAX * FDIM];
__device__ __align__(128) float g_rv [BMAX * FDIM];
__device__ __align__(128) float g_vm [BMAX * FDIM];
__device__ __align__(128) float g_kq [BMAX * FDIM];
__device__ __align__(128) float g_wqT [FDIM * FDIM];
__device__ __align__(128) float g_kWoT[FDIM * FDIM];
__device__ __align__(128) float g_wc  [FDIM * FDIM];
__device__ __align__(128) float g_bq  [FDIM];
__device__ __align__(128) float g_dot[NMAX];
__device__ __align__(128) float g_smax[BMAX];
__device__ __align__(128) float g_inv [BMAX];

__device__ __forceinline__ float actf(float x) {
    return x / (1.0f + expf(-1.702f * x));
}
__device__ __forceinline__ ull ffma2(ull a, ull b, ull c) {
    ull d;
    asm("fma.rn.f32x2 %0, %1, %2, %3;" : "=l"(d) : "l"(a), "l"(b), "l"(c));
    return d;
}
__device__ __forceinline__ float pairsum(ull v) {
    float2 f = *(float2*)&v;
    return f.x + f.y;
}
__device__ __forceinline__ float dot4(float4 a, float4 b) {
    return a.x * b.x + a.y * b.y + a.z * b.z + a.w * b.w;
}

// ---------------- transpose 256x256 ----------------
__global__ void transpose256_kernel(const float* __restrict__ in, float* __restrict__ out) {
    __shared__ float tile[32][33];
    int bx = (blockIdx.x & 7) * 32;
    int by = (blockIdx.x >> 3) * 32;
    int tx = threadIdx.x & 31, ty = threadIdx.x >> 5;
    #pragma unroll
    for (int i = 0; i < 32; i += 8)
        tile[ty + i][tx] = in[(size_t)(by + ty + i) * 256 + bx + tx];
    __syncthreads();
    #pragma unroll
    for (int i = 0; i < 32; i += 8)
        out[(size_t)(bx + ty + i) * 256 + by + tx] = tile[tx][ty + i];
}

// ---------------- bq = kbo @ Wq ----------------
__global__ void bq_kernel(const float* __restrict__ kbo, const float* __restrict__ Wq,
                          float* __restrict__ bq) {
    __shared__ float s[256];
    int t = threadIdx.x;
    s[t] = kbo[t];
    __syncthreads();
    float a0 = 0.f, a1 = 0.f, a2 = 0.f, a3 = 0.f;
    #pragma unroll 4
    for (int n = 0; n < 256; n += 4) {
        a0 += s[n + 0] * Wq[(size_t)(n + 0) * 256 + t];
        a1 += s[n + 1] * Wq[(size_t)(n + 1) * 256 + t];
        a2 += s[n + 2] * Wq[(size_t)(n + 2) * 256 + t];
        a3 += s[n + 3] * Wq[(size_t)(n + 3) * 256 + t];
    }
    bq[t] = (a0 + a1) + (a2 + a3);
}

// ================= col-tiled layer GEMM (register double-buffered) =================
// C[row0+r][f0+c] = post( A[row0+r,:] . W[f0+c,:] + bias[f0+c] )
// grid: (8 colTiles, rowTiles(RT), 1). block 256: warp = 4 rows, lane = col.
// mode bits: 1 = A is entry rank1 act(E*ewf+ebf); 2 = add rank1 residual in epilogue;
//            4 = apply act.
__global__ __launch_bounds__(256, 2)
void layer_kernel(const float* __restrict__ A,
                  const float* __restrict__ W,
                  const float* __restrict__ bias,
                  const float* __restrict__ E,
                  const float* __restrict__ ewf, const float* __restrict__ ebf,
                  float* __restrict__ C,
                  int B, int mode) {
    extern __shared__ __align__(16) float sm[];
    float* sW = sm;                 // 32 x WST
    float* sA = sm + 32 * WST;      // RT x 256

    int t    = threadIdx.x;
    int f0   = blockIdx.x * 32;
    int row0 = blockIdx.y * RT;

    // ---- stage W tile: rows f0..f0+31, all 256 k (coalesced LDG.128 -> STS.128) ----
    {
        const float4* W4 = (const float4*)W;
        #pragma unroll
        for (int i = 0; i < 8; i++) {
            int idx = i * 256 + t;      // 0..2047
            int row = idx >> 6;
            int k4  = idx & 63;
            float4 v = W4[(size_t)(f0 + row) * 64 + k4];
            *(float4*)(sW + row * WST + k4 * 4) = v;
        }
    }

    // ---- stage A tile: rows row0..row0+RT-1 ----
    if (mode & 1) {
        const float4* ew4 = (const float4*)ewf;
        const float4* eb4 = (const float4*)ebf;
        #pragma unroll
        for (int i = 0; i < RT * 64 / 256; i++) {
            int idx = i * 256 + t;
            int r   = idx >> 6;
            int k4  = idx & 63;
            float e = (row0 + r < B) ? __ldg(E + row0 + r) : 0.f;
            float4 w = __ldg(ew4 + k4);
            float4 bb = ebf ? __ldg(eb4 + k4) : make_float4(0.f, 0.f, 0.f, 0.f);
            float4 o;
            o.x = actf(e * w.x + bb.x);
            o.y = actf(e * w.y + bb.y);
            o.z = actf(e * w.z + bb.z);
            o.w = actf(e * w.w + bb.w);
            *(float4*)(sA + r * 256 + k4 * 4) = o;
        }
    } else {
        const float4* A4 = (const float4*)A;
        #pragma unroll
        for (int i = 0; i < RT * 64 / 256; i++) {
            int idx = i * 256 + t;
            int r   = idx >> 6;
            int k4  = idx & 63;
            float4 v;
            if (row0 + r < B) v = A4[(size_t)(row0 + r) * 64 + k4];
            else              v = make_float4(0.f, 0.f, 0.f, 0.f);
            *(float4*)(sA + r * 256 + k4 * 4) = v;
        }
    }
    __syncthreads();

    // ---- compute: warp rq -> rows rq*4..+3; lane c -> col f0+c ----
    int c  = t & 31;
    int rq = t >> 5;
    const float* wr = sW + c * WST;
    const float* ar = sA + (rq * 4) * 256;

    ull acc[4][2] = {{0,0},{0,0},{0,0},{0,0}};

    ulonglong2 w_cur = *(const ulonglong2*)(wr);
    ulonglong2 a_cur[4];
    #pragma unroll
    for (int r = 0; r < 4; r++)
        a_cur[r] = *(const ulonglong2*)(ar + r * 256);

    #pragma unroll
    for (int kk = 0; kk < 64; kk++) {        // 4 k per iter
        ulonglong2 w_nxt;
        ulonglong2 a_nxt[4];
        if (kk < 63) {
            w_nxt = *(const ulonglong2*)(wr + (kk + 1) * 4);
            #pragma unroll
            for (int r = 0; r < 4; r++)
                a_nxt[r] = *(const ulonglong2*)(ar + r * 256 + (kk + 1) * 4);
        }
        #pragma unroll
        for (int r = 0; r < 4; r++) {
            acc[r][0] = ffma2(a_cur[r].x, w_cur.x, acc[r][0]);
            acc[r][1] = ffma2(a_cur[r].y, w_cur.y, acc[r][1]);
        }
        if (kk < 63) {
            w_cur = w_nxt;
            #pragma unroll
            for (int r = 0; r < 4; r++) a_cur[r] = a_nxt[r];
        }
    }

    // ---- epilogue ----
    float o[4];
    #pragma unroll
    for (int r = 0; r < 4; r++)
        o[r] = pairsum(acc[r][0]) + pairsum(acc[r][1]);

    float bb = bias ? __ldg(bias + f0 + c) : 0.f;
    float rw = 0.f, rb = 0.f;
    if (mode & 2) {
        rw = __ldg(ewf + f0 + c);
        if (ebf) rb = __ldg(ebf + f0 + c);
    }
    #pragma unroll
    for (int i = 0; i < 4; i++) {
        int row = row0 + rq * 4 + i;
        if (row >= B) continue;
        float v = o[i] + bb;
        if (mode & 2) v += __ldg(E + row) * rw + rb;
        if (mode & 4) v = actf(v);
        C[(size_t)row * 256 + f0 + c] = v;
    }
}

// ---------------- seg helpers (int32 buffer that may really be int64) ----------------
__device__ __forceinline__ int seg_is64(const int* __restrict__ s, int N) {
    return s[N - 1] == 0;   // sorted, max=B-1>0; int64 LE high word at N-1 is 0
}

// ---------------- dot pass: 32 rows/warp, kq register-cached, streaming x ------------
__global__ void dot_kernel(const float4* __restrict__ x,
                           const int* __restrict__ seg32,
                           const float* __restrict__ kq,
                           float* __restrict__ dotv,
                           int N) {
    int gw   = (blockIdx.x * blockDim.x + threadIdx.x) >> 5;
    int lane = threadIdx.x & 31;
    int row0 = gw * 32;
    if (row0 >= N) return;
    int st = seg_is64(seg32, N) ? 2 : 1;

    int rlast = row0 + 31 < N ? row0 + 31 : N - 1;
    int b0    = seg32[(size_t)row0 * st];
    int blast = seg32[(size_t)rlast * st];

    if (b0 == blast && row0 + 32 <= N) {
        const float4* kr = (const float4*)kq + (size_t)b0 * 64;
        float4 k0 = kr[lane], k1 = kr[lane + 32];
        float myres = 0.f;
        #pragma unroll
        for (int batch = 0; batch < 4; batch++) {
            float4 xa[8], xb[8];
            #pragma unroll
            for (int r = 0; r < 8; r++) {
                const float4* xr = x + (size_t)(row0 + batch * 8 + r) * 64;
                xa[r] = __ldcs(xr + lane);
                xb[r] = __ldcs(xr + lane + 32);
            }
            float s[8];
            #pragma unroll
            for (int r = 0; r < 8; r++)
                s[r] = dot4(xa[r], k0) + dot4(xb[r], k1);
            #pragma unroll
            for (int o = 16; o; o >>= 1) {
                #pragma unroll
                for (int r = 0; r < 8; r++)
                    s[r] += __shfl_xor_sync(0xffffffffu, s[r], o);
            }
            #pragma unroll
            for (int r = 0; r < 8; r++)
                if (lane == batch * 8 + r) myres = s[r];
        }
        dotv[row0 + lane] = myres;
    } else {
        int nrows = N - row0; if (nrows > 32) nrows = 32;
        int myrow = row0 + lane;
        int rload = myrow < N ? myrow : N - 1;
        int bl = seg32[(size_t)rload * st];
        int bcur = -1;
        float4 k0, k1;
        float myres = 0.f;
        for (int r = 0; r < nrows; r++) {
            int b = __shfl_sync(0xffffffffu, bl, r);
            if (b != bcur) {
                const float4* kr = (const float4*)kq + (size_t)b * 64;
                k0 = kr[lane]; k1 = kr[lane + 32];
                bcur = b;
            }
            const float4* xr = x + (size_t)(row0 + r) * 64;
            float4 a0 = __ldcs(xr + lane), a1 = __ldcs(xr + lane + 32);
            float s = dot4(a0, k0) + dot4(a1, k1);
            #pragma unroll
            for (int o = 16; o; o >>= 1) s += __shfl_xor_sync(0xffffffffu, s, o);
            if (lane == r) myres = s;
        }
        if (myrow < N) dotv[myrow] = myres;
    }
}

// ---------------- segment reduce (deterministic, per-segment block) ----------------
__device__ __forceinline__ int lowerb(const int* __restrict__ s, int n, int v, int st) {
    int lo = 0, hi = n;
    while (lo < hi) {
        int mid = (lo + hi) >> 1;
        if (s[(size_t)mid * st] < v) lo = mid + 1; else hi = mid;
    }
    return lo;
}

__global__ void segreduce_kernel(const int* __restrict__ seg32,
                                 const float* __restrict__ dotv,
                                 float* __restrict__ smax,
                                 float* __restrict__ invnorm,
                                 int N, float scale) {
    __shared__ float red[256];
    __shared__ int sse[2];
    int b = blockIdx.x;
    int t = threadIdx.x;
    if (t == 0) {
        int st = seg_is64(seg32, N) ? 2 : 1;
        sse[0] = lowerb(seg32, N, b, st);
        sse[1] = lowerb(seg32, N, b + 1, st);
    }
    __syncthreads();
    int start = sse[0], end = sse[1];

    float m = -3.4e38f;
    for (int i = start + t; i < end; i += 256) m = fmaxf(m, dotv[i]);
    red[t] = m;
    __syncthreads();
    #pragma unroll
    for (int s = 128; s; s >>= 1) {
        if (t < s) red[t] = fmaxf(red[t], red[t + s]);
        __syncthreads();
    }
    float mx = red[0];
    __syncthreads();

    float ss = 0.f;
    for (int i = start + t; i < end; i += 256) ss += expf((dotv[i] - mx) * scale);
    red[t] = ss;
    __syncthreads();
    #pragma unroll
    for (int s = 128; s; s >>= 1) {
        if (t < s) red[t] += red[t + s];
        __syncthreads();
    }
    if (t == 0) {
        smax[b] = mx;
        invnorm[b] = 1.f / (red[0] + 1e-8f);
    }
}

// ---------------- output pass: 32 rows/warp, vm register-cached, streaming stores ----
__global__ void out_kernel(const float* __restrict__ dotv,
                           const int* __restrict__ seg32,
                           const float* __restrict__ vm,
                           const float* __restrict__ smax,
                           const float* __restrict__ invnorm,
                           float4* __restrict__ out,
                           int N, float scale) {
    int gw   = (blockIdx.x * blockDim.x + threadIdx.x) >> 5;
    int lane = threadIdx.x & 31;
    int row0 = gw * 32;
    if (row0 >= N) return;
    int st = seg_is64(seg32, N) ? 2 : 1;

    int myrow = row0 + lane;
    int bl = 0; float cl = 0.f;
    if (myrow < N) {
        bl = seg32[(size_t)myrow * st];
        cl = expf((dotv[myrow] - smax[bl]) * scale) * invnorm[bl];
    }

    int nrows = N - row0; if (nrows > 32) nrows = 32;
    int bcur = -1;
    float4 v0, v1;
    for (int r = 0; r < nrows; r++) {
        int b     = __shfl_sync(0xffffffffu, bl, r);
        float cf  = __shfl_sync(0xffffffffu, cl, r);
        if (b != bcur) {
            const float4* vr = (const float4*)vm + (size_t)b * 64;
            v0 = vr[lane];
            v1 = vr[lane + 32];
            bcur = b;
        }
        float4 o0 = make_float4(v0.x * cf, v0.y * cf, v0.z * cf, v0.w * cf);
        float4 o1 = make_float4(v1.x * cf, v1.y * cf, v1.z * cf, v1.w * cf);
        float4* orow = out + (size_t)(row0 + r) * 64;
        __stcs(orow + lane, o0);
        __stcs(orow + lane + 32, o1);
    }
}

// ---------------- launcher ----------------
extern "C" void kernel_launch(void* const* d_in, const int* in_sizes, int n_in,
                              void* d_out, int out_size) {
    int sh = (n_in >= 17) ? 0 : 1;
    const float* x    = (const float*)d_in[0];
    const float* E    = (const float*)d_in[1];
    const int*   seg  = (const int*)  d_in[3 - sh];
    const float* Wq   = (const float*)d_in[4 - sh];
    const float* Wkf  = (const float*)d_in[5 - sh];
    const float* bkf  = (const float*)d_in[6 - sh];
    const float* Wvf  = (const float*)d_in[7 - sh];
    const float* kW1  = (const float*)d_in[8 - sh];
    const float* kb1  = (const float*)d_in[9 - sh];
    const float* kW2  = (const float*)d_in[10 - sh];
    const float* kb2  = (const float*)d_in[11 - sh];
    const float* kWo  = (const float*)d_in[12 - sh];
    const float* kbo  = (const float*)d_in[13 - sh];
    const float* vW1  = (const float*)d_in[14 - sh];
    const float* vW2  = (const float*)d_in[15 - sh];
    const float* vWo  = (const float*)d_in[16 - sh];

    int B = in_sizes[1];
    int N = in_sizes[3 - sh];
    float scale = 1.f / 16.f;   // 1/sqrt(256)

    float *t1k, *t1v, *rk, *rv, *vm, *kq, *wqT, *kWoT, *wc, *bq, *dotv, *smax, *inv;
    cudaGetSymbolAddress((void**)&t1k, g_t1k);
    cudaGetSymbolAddress((void**)&t1v, g_t1v);
    cudaGetSymbolAddress((void**)&rk,  g_rk);
    cudaGetSymbolAddress((void**)&rv,  g_rv);
    cudaGetSymbolAddress((void**)&vm,  g_vm);
    cudaGetSymbolAddress((void**)&kq,  g_kq);
    cudaGetSymbolAddress((void**)&wqT, g_wqT);
    cudaGetSymbolAddress((void**)&kWoT, g_kWoT);
    cudaGetSymbolAddress((void**)&wc,  g_wc);
    cudaGetSymbolAddress((void**)&bq,  g_bq);
    cudaGetSymbolAddress((void**)&dotv, g_dot);
    cudaGetSymbolAddress((void**)&smax, g_smax);
    cudaGetSymbolAddress((void**)&inv,  g_inv);

    const int LS = (32 * WST + RT * 256) * (int)sizeof(float);   // 66048 B
    cudaFuncSetAttribute(layer_kernel, cudaFuncAttributeMaxDynamicSharedMemorySize, LS);

    // side stream + events (created once on the uncaptured correctness call;
    // capture sees only record/wait nodes — identical work every call)
    static cudaStream_t s_side = nullptr;
    static cudaEvent_t  s_fork = nullptr, s_wc = nullptr, s_join = nullptr;
    if (!s_side) {
        cudaStreamCreateWithFlags(&s_side, cudaStreamNonBlocking);
        cudaEventCreateWithFlags(&s_fork, cudaEventDisableTiming);
        cudaEventCreateWithFlags(&s_wc,   cudaEventDisableTiming);
        cudaEventCreateWithFlags(&s_join, cudaEventDisableTiming);
    }

    int rowTiles = (B + RT - 1) / RT;
    dim3 lgrid(8, rowTiles, 1);

    // ---- fork ----
    cudaEventRecord(s_fork, 0);
    cudaStreamWaitEvent(s_side, s_fork, 0);

    // ---- side stream: Wq/kWo prep, Wc, bq, then v-branch ----
    transpose256_kernel<<<64, 256, 0, s_side>>>(Wq, wqT);
    transpose256_kernel<<<64, 256, 0, s_side>>>(kWo, kWoT);
    {
        // Wc[c][k] = sum_n Wq[n][c] * kWo[n][k]  (A=wqT, W=kWoT)
        dim3 wg(8, 8, 1);
        layer_kernel<<<wg, 256, LS, s_side>>>(wqT, kWoT, nullptr, nullptr,
                                              nullptr, nullptr, wc, 256, 0);
    }
    bq_kernel<<<1, 256, 0, s_side>>>(kbo, Wq, bq);
    cudaEventRecord(s_wc, s_side);

    layer_kernel<<<lgrid, 256, LS, s_side>>>(nullptr, vW1, nullptr, E,
                                             Wvf, nullptr, t1v, B, 1 | 4);
    layer_kernel<<<lgrid, 256, LS, s_side>>>(t1v, vW2, nullptr, E,
                                             Wvf, nullptr, rv, B, 2 | 4);
    layer_kernel<<<lgrid, 256, LS, s_side>>>(rv, vWo, nullptr, E,
                                             nullptr, nullptr, vm, B, 0);
    cudaEventRecord(s_join, s_side);

    // ---- main (legacy) stream: k-branch (3 layers) -> dot -> segreduce ----
    layer_kernel<<<lgrid, 256, LS>>>(nullptr, kW1, kb1, E,
                                     Wkf, bkf, t1k, B, 1 | 4);
    layer_kernel<<<lgrid, 256, LS>>>(t1k, kW2, kb2, E,
                                     Wkf, bkf, rk, B, 2 | 4);
    cudaStreamWaitEvent(0, s_wc, 0);
    layer_kernel<<<lgrid, 256, LS>>>(rk, wc, bq, E,
                                     nullptr, nullptr, kq, B, 0);

    {
        int warps = (N + 31) / 32;
        int blocks = (warps * 32 + 255) / 256;
        dot_kernel<<<blocks, 256>>>((const float4*)x, seg, kq, dotv, N);
    }
    segreduce_kernel<<<B, 256>>>(seg, dotv, smax, inv, N, scale);

    // ---- join: out needs vm from the side stream ----
    cudaStreamWaitEvent(0, s_join, 0);
    {
        int warps = (N + 31) / 32;
        int blocks = (warps * 32 + 255) / 256;
        out_kernel<<<blocks, 256>>>(dotv, seg, vm, smax, inv, (float4*)d_out, N, scale);
    }
}

// round 16
// speedup vs baseline: 1.0519x; 1.0019x over previous
#include <cuda_runtime.h>
#include <math.h>

#define FDIM 256
#define BMAX 1024
#define NMAX 1048576
#define WST 260           // sW stride (256 data + 4 pad): 16B-aligned, conflict-free LDS.128
#define RT 32             // rows per CTA tile

typedef unsigned long long ull;

// ---------------- scratch (static device globals; no allocation) ----------------
__device__ __align__(128) float g_t1k[BMAX * FDIM];
__device__ __align__(128) float g_t1v[BMAX * FDIM];
__device__ __align__(128) float g_rk [BMAX * FDIM];
__device__ __align__(128) float g_rv [BMAX * FDIM];
__device__ __align__(128) float g_vm [BMAX * FDIM];
__device__ __align__(128) float g_kq [BMAX * FDIM];
__device__ __align__(128) float g_wqT [FDIM * FDIM];
__device__ __align__(128) float g_kWoT[FDIM * FDIM];
__device__ __align__(128) float g_wc  [FDIM * FDIM];
__device__ __align__(128) float g_bq  [FDIM];
__device__ __align__(128) float g_dot[NMAX];
__device__ __align__(128) float g_smax[BMAX];
__device__ __align__(128) float g_inv [BMAX];

__device__ __forceinline__ float actf(float x) {
    return x / (1.0f + expf(-1.702f * x));
}
__device__ __forceinline__ ull ffma2(ull a, ull b, ull c) {
    ull d;
    asm("fma.rn.f32x2 %0, %1, %2, %3;" : "=l"(d) : "l"(a), "l"(b), "l"(c));
    return d;
}
__device__ __forceinline__ float pairsum(ull v) {
    float2 f = *(float2*)&v;
    return f.x + f.y;
}
__device__ __forceinline__ float dot4(float4 a, float4 b) {
    return a.x * b.x + a.y * b.y + a.z * b.z + a.w * b.w;
}

// ---------------- fused dual transpose 256x256 ----------------
// blocks 0..63: in0->out0 ; blocks 64..127: in1->out1
__global__ void transpose2_kernel(const float* __restrict__ in0, float* __restrict__ out0,
                                  const float* __restrict__ in1, float* __restrict__ out1) {
    __shared__ float tile[32][33];
    int blk = blockIdx.x & 63;
    const float* in  = (blockIdx.x < 64) ? in0  : in1;
    float*       out = (blockIdx.x < 64) ? out0 : out1;
    int bx = (blk & 7) * 32;
    int by = (blk >> 3) * 32;
    int tx = threadIdx.x & 31, ty = threadIdx.x >> 5;
    #pragma unroll
    for (int i = 0; i < 32; i += 8)
        tile[ty + i][tx] = in[(size_t)(by + ty + i) * 256 + bx + tx];
    __syncthreads();
    #pragma unroll
    for (int i = 0; i < 32; i += 8)
        out[(size_t)(bx + ty + i) * 256 + by + tx] = tile[tx][ty + i];
}

// ---------------- bq = kbo @ Wq (parallelized, deterministic) ----------------
// grid 8 x 256 threads. Block b owns outputs f = 32b..32b+31.
// Warp w accumulates n-slice [32w, 32w+32); 8 partials reduced in fixed order.
__global__ void bq_kernel(const float* __restrict__ kbo, const float* __restrict__ Wq,
                          float* __restrict__ bq) {
    __shared__ float part[8][32];
    int t = threadIdx.x;
    int lane = t & 31, w = t >> 5;
    int f = blockIdx.x * 32 + lane;
    float s = 0.f;
    #pragma unroll 8
    for (int i = 0; i < 32; i++) {
        int n = w * 32 + i;
        s += __ldg(kbo + n) * __ldg(Wq + (size_t)n * FDIM + f);
    }
    part[w][lane] = s;
    __syncthreads();
    if (w == 0) {
        float tot = 0.f;
        #pragma unroll
        for (int j = 0; j < 8; j++) tot += part[j][lane];
        bq[f] = tot;
    }
}

// ================= col-tiled layer GEMM (register double-buffered) =================
// C[row0+r][f0+c] = post( A[row0+r,:] . W[f0+c,:] + bias[f0+c] )
// grid: (8 colTiles, rowTiles(RT), 1). block 256: warp = 4 rows, lane = col.
// mode bits: 1 = A is entry rank1 act(E*ewf+ebf); 2 = add rank1 residual in epilogue;
//            4 = apply act.
__global__ __launch_bounds__(256, 2)
void layer_kernel(const float* __restrict__ A,
                  const float* __restrict__ W,
                  const float* __restrict__ bias,
                  const float* __restrict__ E,
                  const float* __restrict__ ewf, const float* __restrict__ ebf,
                  float* __restrict__ C,
                  int B, int mode) {
    extern __shared__ __align__(16) float sm[];
    float* sW = sm;                 // 32 x WST
    float* sA = sm + 32 * WST;      // RT x 256

    int t    = threadIdx.x;
    int f0   = blockIdx.x * 32;
    int row0 = blockIdx.y * RT;

    // ---- stage W tile: rows f0..f0+31, all 256 k (coalesced LDG.128 -> STS.128) ----
    {
        const float4* W4 = (const float4*)W;
        #pragma unroll
        for (int i = 0; i < 8; i++) {
            int idx = i * 256 + t;      // 0..2047
            int row = idx >> 6;
            int k4  = idx & 63;
            float4 v = W4[(size_t)(f0 + row) * 64 + k4];
            *(float4*)(sW + row * WST + k4 * 4) = v;
        }
    }

    // ---- stage A tile: rows row0..row0+RT-1 ----
    if (mode & 1) {
        const float4* ew4 = (const float4*)ewf;
        const float4* eb4 = (const float4*)ebf;
        #pragma unroll
        for (int i = 0; i < RT * 64 / 256; i++) {
            int idx = i * 256 + t;
            int r   = idx >> 6;
            int k4  = idx & 63;
            float e = (row0 + r < B) ? __ldg(E + row0 + r) : 0.f;
            float4 w = __ldg(ew4 + k4);
            float4 bb = ebf ? __ldg(eb4 + k4) : make_float4(0.f, 0.f, 0.f, 0.f);
            float4 o;
            o.x = actf(e * w.x + bb.x);
            o.y = actf(e * w.y + bb.y);
            o.z = actf(e * w.z + bb.z);
            o.w = actf(e * w.w + bb.w);
            *(float4*)(sA + r * 256 + k4 * 4) = o;
        }
    } else {
        const float4* A4 = (const float4*)A;
        #pragma unroll
        for (int i = 0; i < RT * 64 / 256; i++) {
            int idx = i * 256 + t;
            int r   = idx >> 6;
            int k4  = idx & 63;
            float4 v;
            if (row0 + r < B) v = A4[(size_t)(row0 + r) * 64 + k4];
            else              v = make_float4(0.f, 0.f, 0.f, 0.f);
            *(float4*)(sA + r * 256 + k4 * 4) = v;
        }
    }
    __syncthreads();

    // ---- compute: warp rq -> rows rq*4..+3; lane c -> col f0+c ----
    int c  = t & 31;
    int rq = t >> 5;
    const float* wr = sW + c * WST;
    const float* ar = sA + (rq * 4) * 256;

    ull acc[4][2] = {{0,0},{0,0},{0,0},{0,0}};

    ulonglong2 w_cur = *(const ulonglong2*)(wr);
    ulonglong2 a_cur[4];
    #pragma unroll
    for (int r = 0; r < 4; r++)
        a_cur[r] = *(const ulonglong2*)(ar + r * 256);

    #pragma unroll
    for (int kk = 0; kk < 64; kk++) {        // 4 k per iter
        ulonglong2 w_nxt;
        ulonglong2 a_nxt[4];
        if (kk < 63) {
            w_nxt = *(const ulonglong2*)(wr + (kk + 1) * 4);
            #pragma unroll
            for (int r = 0; r < 4; r++)
                a_nxt[r] = *(const ulonglong2*)(ar + r * 256 + (kk + 1) * 4);
        }
        #pragma unroll
        for (int r = 0; r < 4; r++) {
            acc[r][0] = ffma2(a_cur[r].x, w_cur.x, acc[r][0]);
            acc[r][1] = ffma2(a_cur[r].y, w_cur.y, acc[r][1]);
        }
        if (kk < 63) {
            w_cur = w_nxt;
            #pragma unroll
            for (int r = 0; r < 4; r++) a_cur[r] = a_nxt[r];
        }
    }

    // ---- epilogue ----
    float o[4];
    #pragma unroll
    for (int r = 0; r < 4; r++)
        o[r] = pairsum(acc[r][0]) + pairsum(acc[r][1]);

    float bb = bias ? __ldg(bias + f0 + c) : 0.f;
    float rw = 0.f, rb = 0.f;
    if (mode & 2) {
        rw = __ldg(ewf + f0 + c);
        if (ebf) rb = __ldg(ebf + f0 + c);
    }
    #pragma unroll
    for (int i = 0; i < 4; i++) {
        int row = row0 + rq * 4 + i;
        if (row >= B) continue;
        float v = o[i] + bb;
        if (mode & 2) v += __ldg(E + row) * rw + rb;
        if (mode & 4) v = actf(v);
        C[(size_t)row * 256 + f0 + c] = v;
    }
}

// ---------------- seg helpers (int32 buffer that may really be int64) ----------------
__device__ __forceinline__ int seg_is64(const int* __restrict__ s, int N) {
    return s[N - 1] == 0;   // sorted, max=B-1>0; int64 LE high word at N-1 is 0
}

// ---------------- dot pass: 32 rows/warp, kq register-cached, streaming x ------------
__global__ void dot_kernel(const float4* __restrict__ x,
                           const int* __restrict__ seg32,
                           const float* __restrict__ kq,
                           float* __restrict__ dotv,
                           int N) {
    int gw   = (blockIdx.x * blockDim.x + threadIdx.x) >> 5;
    int lane = threadIdx.x & 31;
    int row0 = gw * 32;
    if (row0 >= N) return;
    int st = seg_is64(seg32, N) ? 2 : 1;

    int rlast = row0 + 31 < N ? row0 + 31 : N - 1;
    int b0    = seg32[(size_t)row0 * st];
    int blast = seg32[(size_t)rlast * st];

    if (b0 == blast && row0 + 32 <= N) {
        const float4* kr = (const float4*)kq + (size_t)b0 * 64;
        float4 k0 = kr[lane], k1 = kr[lane + 32];
        float myres = 0.f;
        #pragma unroll
        for (int batch = 0; batch < 4; batch++) {
            float4 xa[8], xb[8];
            #pragma unroll
            for (int r = 0; r < 8; r++) {
                const float4* xr = x + (size_t)(row0 + batch * 8 + r) * 64;
                xa[r] = __ldcs(xr + lane);
                xb[r] = __ldcs(xr + lane + 32);
            }
            float s[8];
            #pragma unroll
            for (int r = 0; r < 8; r++)
                s[r] = dot4(xa[r], k0) + dot4(xb[r], k1);
            #pragma unroll
            for (int o = 16; o; o >>= 1) {
                #pragma unroll
                for (int r = 0; r < 8; r++)
                    s[r] += __shfl_xor_sync(0xffffffffu, s[r], o);
            }
            #pragma unroll
            for (int r = 0; r < 8; r++)
                if (lane == batch * 8 + r) myres = s[r];
        }
        dotv[row0 + lane] = myres;
    } else {
        int nrows = N - row0; if (nrows > 32) nrows = 32;
        int myrow = row0 + lane;
        int rload = myrow < N ? myrow : N - 1;
        int bl = seg32[(size_t)rload * st];
        int bcur = -1;
        float4 k0, k1;
        float myres = 0.f;
        for (int r = 0; r < nrows; r++) {
            int b = __shfl_sync(0xffffffffu, bl, r);
            if (b != bcur) {
                const float4* kr = (const float4*)kq + (size_t)b * 64;
                k0 = kr[lane]; k1 = kr[lane + 32];
                bcur = b;
            }
            const float4* xr = x + (size_t)(row0 + r) * 64;
            float4 a0 = __ldcs(xr + lane), a1 = __ldcs(xr + lane + 32);
            float s = dot4(a0, k0) + dot4(a1, k1);
            #pragma unroll
            for (int o = 16; o; o >>= 1) s += __shfl_xor_sync(0xffffffffu, s, o);
            if (lane == r) myres = s;
        }
        if (myrow < N) dotv[myrow] = myres;
    }
}

// ---------------- segment reduce (deterministic, per-segment block) ----------------
__device__ __forceinline__ int lowerb(const int* __restrict__ s, int n, int v, int st) {
    int lo = 0, hi = n;
    while (lo < hi) {
        int mid = (lo + hi) >> 1;
        if (s[(size_t)mid * st] < v) lo = mid + 1; else hi = mid;
    }
    return lo;
}

__global__ void segreduce_kernel(const int* __restrict__ seg32,
                                 const float* __restrict__ dotv,
                                 float* __restrict__ smax,
                                 float* __restrict__ invnorm,
                                 int N, float scale) {
    __shared__ float red[256];
    __shared__ int sse[2];
    int b = blockIdx.x;
    int t = threadIdx.x;
    if (t == 0) {
        int st = seg_is64(seg32, N) ? 2 : 1;
        sse[0] = lowerb(seg32, N, b, st);
        sse[1] = lowerb(seg32, N, b + 1, st);
    }
    __syncthreads();
    int start = sse[0], end = sse[1];

    float m = -3.4e38f;
    for (int i = start + t; i < end; i += 256) m = fmaxf(m, dotv[i]);
    red[t] = m;
    __syncthreads();
    #pragma unroll
    for (int s = 128; s; s >>= 1) {
        if (t < s) red[t] = fmaxf(red[t], red[t + s]);
        __syncthreads();
    }
    float mx = red[0];
    __syncthreads();

    float ss = 0.f;
    for (int i = start + t; i < end; i += 256) ss += expf((dotv[i] - mx) * scale);
    red[t] = ss;
    __syncthreads();
    #pragma unroll
    for (int s = 128; s; s >>= 1) {
        if (t < s) red[t] += red[t + s];
        __syncthreads();
    }
    if (t == 0) {
        smax[b] = mx;
        invnorm[b] = 1.f / (red[0] + 1e-8f);
    }
}

// ---------------- output pass: 32 rows/warp, vm register-cached, streaming stores ----
__global__ void out_kernel(const float* __restrict__ dotv,
                           const int* __restrict__ seg32,
                           const float* __restrict__ vm,
                           const float* __restrict__ smax,
                           const float* __restrict__ invnorm,
                           float4* __restrict__ out,
                           int N, float scale) {
    int gw   = (blockIdx.x * blockDim.x + threadIdx.x) >> 5;
    int lane = threadIdx.x & 31;
    int row0 = gw * 32;
    if (row0 >= N) return;
    int st = seg_is64(seg32, N) ? 2 : 1;

    int myrow = row0 + lane;
    int bl = 0; float cl = 0.f;
    if (myrow < N) {
        bl = seg32[(size_t)myrow * st];
        cl = expf((dotv[myrow] - smax[bl]) * scale) * invnorm[bl];
    }

    int nrows = N - row0; if (nrows > 32) nrows = 32;
    int bcur = -1;
    float4 v0, v1;
    for (int r = 0; r < nrows; r++) {
        int b     = __shfl_sync(0xffffffffu, bl, r);
        float cf  = __shfl_sync(0xffffffffu, cl, r);
        if (b != bcur) {
            const float4* vr = (const float4*)vm + (size_t)b * 64;
            v0 = vr[lane];
            v1 = vr[lane + 32];
            bcur = b;
        }
        float4 o0 = make_float4(v0.x * cf, v0.y * cf, v0.z * cf, v0.w * cf);
        float4 o1 = make_float4(v1.x * cf, v1.y * cf, v1.z * cf, v1.w * cf);
        float4* orow = out + (size_t)(row0 + r) * 64;
        __stcs(orow + lane, o0);
        __stcs(orow + lane + 32, o1);
    }
}

// ---------------- launcher ----------------
extern "C" void kernel_launch(void* const* d_in, const int* in_sizes, int n_in,
                              void* d_out, int out_size) {
    int sh = (n_in >= 17) ? 0 : 1;
    const float* x    = (const float*)d_in[0];
    const float* E    = (const float*)d_in[1];
    const int*   seg  = (const int*)  d_in[3 - sh];
    const float* Wq   = (const float*)d_in[4 - sh];
    const float* Wkf  = (const float*)d_in[5 - sh];
    const float* bkf  = (const float*)d_in[6 - sh];
    const float* Wvf  = (const float*)d_in[7 - sh];
    const float* kW1  = (const float*)d_in[8 - sh];
    const float* kb1  = (const float*)d_in[9 - sh];
    const float* kW2  = (const float*)d_in[10 - sh];
    const float* kb2  = (const float*)d_in[11 - sh];
    const float* kWo  = (const float*)d_in[12 - sh];
    const float* kbo  = (const float*)d_in[13 - sh];
    const float* vW1  = (const float*)d_in[14 - sh];
    const float* vW2  = (const float*)d_in[15 - sh];
    const float* vWo  = (const float*)d_in[16 - sh];

    int B = in_sizes[1];
    int N = in_sizes[3 - sh];
    float scale = 1.f / 16.f;   // 1/sqrt(256)

    float *t1k, *t1v, *rk, *rv, *vm, *kq, *wqT, *kWoT, *wc, *bq, *dotv, *smax, *inv;
    cudaGetSymbolAddress((void**)&t1k, g_t1k);
    cudaGetSymbolAddress((void**)&t1v, g_t1v);
    cudaGetSymbolAddress((void**)&rk,  g_rk);
    cudaGetSymbolAddress((void**)&rv,  g_rv);
    cudaGetSymbolAddress((void**)&vm,  g_vm);
    cudaGetSymbolAddress((void**)&kq,  g_kq);
    cudaGetSymbolAddress((void**)&wqT, g_wqT);
    cudaGetSymbolAddress((void**)&kWoT, g_kWoT);
    cudaGetSymbolAddress((void**)&wc,  g_wc);
    cudaGetSymbolAddress((void**)&bq,  g_bq);
    cudaGetSymbolAddress((void**)&dotv, g_dot);
    cudaGetSymbolAddress((void**)&smax, g_smax);
    cudaGetSymbolAddress((void**)&inv,  g_inv);

    const int LS = (32 * WST + RT * 256) * (int)sizeof(float);   // 66048 B
    cudaFuncSetAttribute(layer_kernel, cudaFuncAttributeMaxDynamicSharedMemorySize, LS);

    // side stream + events (created once on the uncaptured correctness call;
    // capture sees only record/wait nodes — identical work every call)
    static cudaStream_t s_side = nullptr;
    static cudaEvent_t  s_fork = nullptr, s_wc = nullptr, s_join = nullptr;
    if (!s_side) {
        cudaStreamCreateWithFlags(&s_side, cudaStreamNonBlocking);
        cudaEventCreateWithFlags(&s_fork, cudaEventDisableTiming);
        cudaEventCreateWithFlags(&s_wc,   cudaEventDisableTiming);
        cudaEventCreateWithFlags(&s_join, cudaEventDisableTiming);
    }

    int rowTiles = (B + RT - 1) / RT;
    dim3 lgrid(8, rowTiles, 1);

    // ---- fork ----
    cudaEventRecord(s_fork, 0);
    cudaStreamWaitEvent(s_side, s_fork, 0);

    // ---- side stream: transposes (fused), bq (parallel), Wc, then v-branch ----
    transpose2_kernel<<<128, 256, 0, s_side>>>(Wq, wqT, kWo, kWoT);
    bq_kernel<<<8, 256, 0, s_side>>>(kbo, Wq, bq);
    {
        // Wc[c][k] = sum_n Wq[n][c] * kWo[n][k]  (A=wqT, W=kWoT)
        dim3 wg(8, 8, 1);
        layer_kernel<<<wg, 256, LS, s_side>>>(wqT, kWoT, nullptr, nullptr,
                                              nullptr, nullptr, wc, 256, 0);
    }
    cudaEventRecord(s_wc, s_side);

    layer_kernel<<<lgrid, 256, LS, s_side>>>(nullptr, vW1, nullptr, E,
                                             Wvf, nullptr, t1v, B, 1 | 4);
    layer_kernel<<<lgrid, 256, LS, s_side>>>(t1v, vW2, nullptr, E,
                                             Wvf, nullptr, rv, B, 2 | 4);
    layer_kernel<<<lgrid, 256, LS, s_side>>>(rv, vWo, nullptr, E,
                                             nullptr, nullptr, vm, B, 0);
    cudaEventRecord(s_join, s_side);

    // ---- main (legacy) stream: k-branch (3 layers) -> dot -> segreduce ----
    layer_kernel<<<lgrid, 256, LS>>>(nullptr, kW1, kb1, E,
                                     Wkf, bkf, t1k, B, 1 | 4);
    layer_kernel<<<lgrid, 256, LS>>>(t1k, kW2, kb2, E,
                                     Wkf, bkf, rk, B, 2 | 4);
    cudaStreamWaitEvent(0, s_wc, 0);
    layer_kernel<<<lgrid, 256, LS>>>(rk, wc, bq, E,
                                     nullptr, nullptr, kq, B, 0);

    {
        int warps = (N + 31) / 32;
        int blocks = (warps * 32 + 255) / 256;
        dot_kernel<<<blocks, 256>>>((const float4*)x, seg, kq, dotv, N);
    }
    segreduce_kernel<<<B, 256>>>(seg, dotv, smax, inv, N, scale);

    // ---- join: out needs vm from the side stream ----
    cudaStreamWaitEvent(0, s_join, 0);
    {
        int warps = (N + 31) / 32;
        int blocks = (warps * 32 + 255) / 256;
        out_kernel<<<blocks, 256>>>(dotv, seg, vm, smax, inv, (float4*)d_out, N, scale);
    }
}